// round 4
// baseline (speedup 1.0000x reference)
#include <cuda_runtime.h>

#define B_ 2
#define DE 128
#define DOo 256
#define T_ 16
#define H_ 64
#define W_ 64
#define NBLK 16384   // T * 32 * 32
#define HWREF 1024   // 32 * 32
#define K_ 32
#define KK 8
#define CAP 2048
#define MEMOUT_ELEMS (B_*DOo*H_*W_)   // 2097152

// ---- scratch (static device globals; no runtime allocation) ----
__device__ float g_mb_in[B_][NBLK][4][DE];    // [b][block][px][c]
__device__ float g_mb_out[B_][NBLK][4][DOo];
__device__ float g_qkT[B_][HWREF][NBLK];      // [b][j][n]
__device__ int   g_sel[B_][HWREF][K_];        // selected block indices (desc-value order)

__device__ __forceinline__ unsigned f2ord(float f) {
    unsigned u = __float_as_uint(f);
    return (u & 0x80000000u) ? ~u : (u | 0x80000000u);
}
__device__ __forceinline__ float ord2f(unsigned k) {
    unsigned u = (k & 0x80000000u) ? (k & 0x7fffffffu) : ~k;
    return __uint_as_float(u);
}

// ============================================================
// Kernel 0: blockify  m[b][c][t][h][w] -> mb[b][n][pm][c]
// ============================================================
__global__ void blockify_kernel(const float* __restrict__ in, int D, int is_out) {
    __shared__ float tile[32][33];
    float* out = is_out ? &g_mb_out[0][0][0][0] : &g_mb_in[0][0][0][0];
    int bx = blockIdx.x;
    int wt = bx & 1;  bx >>= 1;
    int h  = bx & 63; bx >>= 6;
    int t  = bx & 15; bx >>= 4;
    int nct = D >> 5;
    int ct = bx % nct;
    int b  = bx / nct;
    int tx = threadIdx.x, ty = threadIdx.y;
    #pragma unroll
    for (int r = 0; r < 4; r++) {
        int c = (ct << 5) + ty + (r << 3);
        tile[ty + (r << 3)][tx] =
            in[(((b * D + c) * T_ + t) * H_ + h) * W_ + (wt << 5) + tx];
    }
    __syncthreads();
    int hr = h >> 1, im = h & 1;
    #pragma unroll
    for (int r = 0; r < 4; r++) {
        int wi = ty + (r << 3);
        int w  = (wt << 5) + wi;
        int wr = w >> 1, jm = w & 1;
        int n  = t * 1024 + hr * 32 + wr;
        int pm = im * 2 + jm;
        out[((b * NBLK + n) * 4 + pm) * D + (ct << 5) + tx] = tile[tx][wi];
    }
}

// ============================================================
// Kernel 1: transpose qk[b][n][j] -> qkT[b][j][n]
// ============================================================
__global__ void qk_transpose_kernel(const float* __restrict__ qk) {
    __shared__ float tile[32][33];
    int bx = blockIdx.x;
    int jt = bx & 31;  bx >>= 5;
    int nt = bx & 511; bx >>= 9;
    int b  = bx;
    int tx = threadIdx.x, ty = threadIdx.y;
    #pragma unroll
    for (int r = 0; r < 4; r++) {
        int n = (nt << 5) + ty + (r << 3);
        tile[ty + (r << 3)][tx] = qk[(b * NBLK + n) * HWREF + (jt << 5) + tx];
    }
    __syncthreads();
    #pragma unroll
    for (int r = 0; r < 4; r++) {
        int j = (jt << 5) + ty + (r << 3);
        g_qkT[b][j][(nt << 5) + tx] = tile[tx][ty + (r << 3)];
    }
}

// ============================================================
// Kernel 2: exact top-32 per column via RADIX SELECT.
// One CTA (256 thr) per (b,j). 16384 keys staged in 64KB smem
// (order-preserving uint). Per-level nibble histogram in packed
// uint64 register counters (no atomics, no local-mem), block
// reduce, narrow prefix until candidate set <= 768. Then
// warp-aggregated compaction + O(C^2/256) pairwise exact ranking.
// Rank order == jax.lax.top_k (desc value, ties -> lower index).
// Per-thread element ownership is stride-256 => conflict-free LDS.
// ============================================================
__global__ void topk_kernel(float* __restrict__ aux_out, int write_aux) {
    extern __shared__ unsigned sv[];            // 16384 keys
    __shared__ unsigned s_ckey[CAP];
    __shared__ int      s_cidx[CAP];
    __shared__ int      s_ccount;
    __shared__ unsigned s_wcnt[8][16];
    __shared__ unsigned s_cnt[16];

    int col = blockIdx.x;
    int b = col >> 10, j = col & 1023;
    int tid = threadIdx.x;
    int lane = tid & 31, wid = tid >> 5;
    if (tid == 0) s_ccount = 0;

    // load + convert to ordered keys (vectorized)
    const float4* src = (const float4*)(&g_qkT[b][j][0]);
    #pragma unroll
    for (int k = 0; k < 16; k++) {
        float4 v = src[tid + 256 * k];
        uint4 kk;
        kk.x = f2ord(v.x); kk.y = f2ord(v.y);
        kk.z = f2ord(v.z); kk.w = f2ord(v.w);
        ((uint4*)sv)[tid + 256 * k] = kk;
    }
    __syncthreads();

    unsigned maskhi = 0, prefix_hi = 0;
    int krem = K_;

    for (int shift = 28; shift >= 0; shift -= 4) {
        // per-thread nibble histogram in two packed uint64 (8-bit lanes)
        unsigned long long acc0 = 0, acc1 = 0;
        #pragma unroll 8
        for (int i = 0; i < 64; i++) {
            unsigned key = sv[tid + 256 * i];
            if ((key & maskhi) == prefix_hi) {
                int nib = (key >> shift) & 15;
                if (nib < 8) acc0 += 1ull << (nib * 8);
                else         acc1 += 1ull << ((nib - 8) * 8);
            }
        }
        unsigned cnt[16];
        #pragma unroll
        for (int n2 = 0; n2 < 8; n2++) {
            cnt[n2]     = (unsigned)((acc0 >> (n2 * 8)) & 0xff);
            cnt[n2 + 8] = (unsigned)((acc1 >> (n2 * 8)) & 0xff);
        }
        #pragma unroll
        for (int n2 = 0; n2 < 16; n2++) {
            #pragma unroll
            for (int o = 16; o; o >>= 1)
                cnt[n2] += __shfl_xor_sync(0xffffffffu, cnt[n2], o);
        }
        __syncthreads();   // prior-iter consumers of s_wcnt/s_cnt done
        if (lane == 0) {
            #pragma unroll
            for (int n2 = 0; n2 < 16; n2++) s_wcnt[wid][n2] = cnt[n2];
        }
        __syncthreads();
        if (tid < 16) {
            unsigned s = 0;
            #pragma unroll
            for (int w = 0; w < 8; w++) s += s_wcnt[w][tid];
            s_cnt[tid] = s;
        }
        __syncthreads();

        // uniform: pick bucket containing the krem-th largest
        int cum = 0, nibSel = 0;
        for (int n2 = 15; n2 >= 0; n2--) {
            int c = (int)s_cnt[n2];
            if (cum + c >= krem) { nibSel = n2; break; }
            cum += c;
        }
        krem -= cum;
        prefix_hi |= ((unsigned)nibSel) << shift;
        maskhi    |= 0xFu << shift;
        int total = (K_ - krem) + (int)s_cnt[nibSel];
        if (total <= 768 || shift == 0) break;
    }

    // compact all elements with (key & maskhi) >= prefix_hi
    #pragma unroll 4
    for (int i = 0; i < 64; i++) {
        unsigned key = sv[tid + 256 * i];
        bool m = ((key & maskhi) >= prefix_hi);
        unsigned bal = __ballot_sync(0xffffffffu, m);
        if (bal) {
            int leader = __ffs(bal) - 1;
            int pos = 0;
            if (lane == leader) pos = atomicAdd(&s_ccount, __popc(bal));
            pos = __shfl_sync(0xffffffffu, pos, leader);
            if (m) {
                int mypos = pos + __popc(bal & ((1u << lane) - 1u));
                if (mypos < CAP) {
                    s_ckey[mypos] = key;
                    s_cidx[mypos] = tid + 256 * i;
                }
            }
        }
    }
    __syncthreads();

    int C = s_ccount < CAP ? s_ccount : CAP;

    // exact rank among candidates; rank r < 32 => r-th largest
    for (int i = tid; i < C; i += 256) {
        unsigned ki = s_ckey[i];
        int      ii = s_cidx[i];
        int rank = 0;
        for (int jc = 0; jc < C; jc++) {
            unsigned kj = s_ckey[jc];
            int      ij = s_cidx[jc];
            rank += (kj > ki) || (kj == ki && ij < ii);
        }
        if (rank < K_) {
            g_sel[b][j][rank] = ii;
            if (write_aux && rank < KK) {
                int o = (b * HWREF + j) * KK + rank;
                aux_out[MEMOUT_ELEMS + o]                   = (float)ii;
                aux_out[MEMOUT_ELEMS + B_ * HWREF * KK + o] = ord2f(ki);
            }
        }
    }
}

// ============================================================
// Kernel 3: sparse block attention (unchanged from R1)
// ============================================================
__global__ void attn_kernel(const float* __restrict__ q_in, float* __restrict__ out) {
    __shared__ float4 q_s4[4][32];
    __shared__ float4 p_s[128];
    __shared__ int    sel[K_];

    int blk = blockIdx.x;
    int b  = blk >> 10, jq = blk & 1023;
    int hr = jq >> 5,   wr = jq & 31;
    int tid = threadIdx.x;

    if (tid < K_) sel[tid] = g_sel[b][jq][tid];
    if (tid < DE) {
        int c = tid;
        const float* qp = q_in + ((b * DE + c) * H_ + hr * 2) * W_ + wr * 2;
        float2 r0 = *(const float2*)qp;
        float2 r1 = *(const float2*)(qp + W_);
        ((float*)q_s4)[0 * DE + c] = r0.x;
        ((float*)q_s4)[1 * DE + c] = r0.y;
        ((float*)q_s4)[2 * DE + c] = r1.x;
        ((float*)q_s4)[3 * DE + c] = r1.y;
    }
    __syncthreads();

    int wid = tid >> 5, lane = tid & 31;
    float4 q0 = q_s4[0][lane];
    float4 q1 = q_s4[1][lane];
    float4 q2 = q_s4[2][lane];
    float4 q3 = q_s4[3][lane];
    const float scale = 0.08838834764831845f;  // 1/sqrt(128)

    #pragma unroll 4
    for (int mm = 0; mm < 16; mm++) {
        int m  = wid * 16 + mm;
        int ks = m >> 2, pm = m & 3;
        int n  = sel[ks];
        const float4* kp = (const float4*)(&g_mb_in[b][n][pm][0]);
        float4 kv = kp[lane];
        float a0 = kv.x*q0.x + kv.y*q0.y + kv.z*q0.z + kv.w*q0.w;
        float a1 = kv.x*q1.x + kv.y*q1.y + kv.z*q1.z + kv.w*q1.w;
        float a2 = kv.x*q2.x + kv.y*q2.y + kv.z*q2.z + kv.w*q2.w;
        float a3 = kv.x*q3.x + kv.y*q3.y + kv.z*q3.z + kv.w*q3.w;
        #pragma unroll
        for (int o = 16; o; o >>= 1) {
            a0 += __shfl_xor_sync(0xffffffffu, a0, o);
            a1 += __shfl_xor_sync(0xffffffffu, a1, o);
            a2 += __shfl_xor_sync(0xffffffffu, a2, o);
            a3 += __shfl_xor_sync(0xffffffffu, a3, o);
        }
        if (lane == 0)
            p_s[m] = make_float4(a0 * scale, a1 * scale, a2 * scale, a3 * scale);
    }
    __syncthreads();

    if (wid < 4) {
        int p = wid;
        float* ps = (float*)p_s;
        float x0 = ps[(lane      ) * 4 + p];
        float x1 = ps[(lane + 32 ) * 4 + p];
        float x2 = ps[(lane + 64 ) * 4 + p];
        float x3 = ps[(lane + 96 ) * 4 + p];
        float mx = fmaxf(fmaxf(x0, x1), fmaxf(x2, x3));
        #pragma unroll
        for (int o = 16; o; o >>= 1) mx = fmaxf(mx, __shfl_xor_sync(0xffffffffu, mx, o));
        float e0 = __expf(x0 - mx), e1 = __expf(x1 - mx);
        float e2 = __expf(x2 - mx), e3 = __expf(x3 - mx);
        float sm = e0 + e1 + e2 + e3;
        #pragma unroll
        for (int o = 16; o; o >>= 1) sm += __shfl_xor_sync(0xffffffffu, sm, o);
        float inv = 1.0f / sm;
        ps[(lane      ) * 4 + p] = e0 * inv;
        ps[(lane + 32 ) * 4 + p] = e1 * inv;
        ps[(lane + 64 ) * 4 + p] = e2 * inv;
        ps[(lane + 96 ) * 4 + p] = e3 * inv;
    }
    __syncthreads();

    int c = tid;
    float a0 = 0.f, a1 = 0.f, a2 = 0.f, a3 = 0.f;
    #pragma unroll 4
    for (int ks = 0; ks < K_; ks++) {
        int n = sel[ks];
        const float* vbase = &g_mb_out[b][n][0][0];
        #pragma unroll
        for (int pm = 0; pm < 4; pm++) {
            float  v  = vbase[pm * DOo + c];
            float4 pw = p_s[ks * 4 + pm];
            a0 += v * pw.x; a1 += v * pw.y; a2 += v * pw.z; a3 += v * pw.w;
        }
    }
    float* ob = out + ((b * DOo + c) * H_ + hr * 2) * W_ + wr * 2;
    *(float2*)ob        = make_float2(a0, a1);
    *(float2*)(ob + W_) = make_float2(a2, a3);
}

// ============================================================
extern "C" void kernel_launch(void* const* d_in, const int* in_sizes, int n_in,
                              void* d_out, int out_size) {
    const float* m_in  = (const float*)d_in[0];
    const float* m_out = (const float*)d_in[1];
    const float* q_in  = (const float*)d_in[2];
    const float* qk    = (const float*)d_in[3];
    float* out = (float*)d_out;

    int write_aux = (out_size >= MEMOUT_ELEMS + 2 * B_ * HWREF * KK) ? 1 : 0;

    cudaFuncSetAttribute(topk_kernel,
                         cudaFuncAttributeMaxDynamicSharedMemorySize, 65536);

    dim3 tb(32, 8);
    blockify_kernel<<<16384, tb>>>(m_in, DE, 0);
    blockify_kernel<<<32768, tb>>>(m_out, DOo, 1);
    qk_transpose_kernel<<<32768, tb>>>(qk);
    topk_kernel<<<B_ * HWREF, 256, 65536>>>(out, write_aux);
    attn_kernel<<<B_ * HWREF, 256>>>(q_in, out);
}

// round 6
// speedup vs baseline: 1.4225x; 1.4225x over previous
#include <cuda_runtime.h>

#define B_ 2
#define DE 128
#define DOo 256
#define T_ 16
#define H_ 64
#define W_ 64
#define NBLK 16384   // T * 32 * 32
#define HWREF 1024   // 32 * 32
#define K_ 32
#define KK 8
#define CAP 1536
#define THRESH 128
#define MEMOUT_ELEMS (B_*DOo*H_*W_)   // 2097152

// ---- scratch (static device globals; no runtime allocation) ----
__device__ float    g_mb_in[B_][NBLK][4][DE];    // [b][block][px][c]
__device__ float    g_mb_out[B_][NBLK][4][DOo];
__device__ unsigned g_qkT[B_][HWREF][NBLK];      // ORDERED KEYS [b][j][n]
__device__ int      g_sel[B_][HWREF][K_];        // selected blocks (desc-value order)

__device__ __forceinline__ unsigned f2ord(float f) {
    unsigned u = __float_as_uint(f);
    return (u & 0x80000000u) ? ~u : (u | 0x80000000u);
}
__device__ __forceinline__ float ord2f(unsigned k) {
    unsigned u = (k & 0x80000000u) ? (k & 0x7fffffffu) : ~k;
    return __uint_as_float(u);
}

// ============================================================
// Kernel 0: blockify  m[b][c][t][h][w] -> mb[b][n][pm][c]
// ============================================================
__global__ void blockify_kernel(const float* __restrict__ in, int D, int is_out) {
    __shared__ float tile[32][33];
    float* out = is_out ? &g_mb_out[0][0][0][0] : &g_mb_in[0][0][0][0];
    int bx = blockIdx.x;
    int wt = bx & 1;  bx >>= 1;
    int h  = bx & 63; bx >>= 6;
    int t  = bx & 15; bx >>= 4;
    int nct = D >> 5;
    int ct = bx % nct;
    int b  = bx / nct;
    int tx = threadIdx.x, ty = threadIdx.y;
    #pragma unroll
    for (int r = 0; r < 4; r++) {
        int c = (ct << 5) + ty + (r << 3);
        tile[ty + (r << 3)][tx] =
            in[(((b * D + c) * T_ + t) * H_ + h) * W_ + (wt << 5) + tx];
    }
    __syncthreads();
    int hr = h >> 1, im = h & 1;
    #pragma unroll
    for (int r = 0; r < 4; r++) {
        int wi = ty + (r << 3);
        int w  = (wt << 5) + wi;
        int wr = w >> 1, jm = w & 1;
        int n  = t * 1024 + hr * 32 + wr;
        int pm = im * 2 + jm;
        out[((b * NBLK + n) * 4 + pm) * D + (ct << 5) + tx] = tile[tx][wi];
    }
}

// ============================================================
// Kernel 1: transpose + key-convert  qk[b][n][j] -> qkT[b][j][n]
// stores order-preserving unsigned keys (f2ord folded in; free on
// a bandwidth-bound transpose)
// ============================================================
__global__ void qk_transpose_kernel(const float* __restrict__ qk) {
    __shared__ unsigned tile[32][33];
    int bx = blockIdx.x;
    int jt = bx & 31;  bx >>= 5;
    int nt = bx & 511; bx >>= 9;
    int b  = bx;
    int tx = threadIdx.x, ty = threadIdx.y;
    #pragma unroll
    for (int r = 0; r < 4; r++) {
        int n = (nt << 5) + ty + (r << 3);
        tile[ty + (r << 3)][tx] = f2ord(qk[(b * NBLK + n) * HWREF + (jt << 5) + tx]);
    }
    __syncthreads();
    #pragma unroll
    for (int r = 0; r < 4; r++) {
        int j = (jt << 5) + ty + (r << 3);
        g_qkT[b][j][(nt << 5) + tx] = tile[tx][ty + (r << 3)];
    }
}

// ============================================================
// Kernel 2: exact top-32 per column via MULTI-PASS RADIX SELECT
// scanning GLOBAL memory directly (no 64KB smem staging -> 8
// CTAs/SM). Pass 1 reads DRAM; later passes + compaction hit L2
// (concurrent working set ~20MB << 126MB L2). Narrow the prefix
// until candidate count <= THRESH, compact via rare smem atomics,
// then exact pairwise rank (desc value, ties -> lower index ==
// jax.lax.top_k order).
// ============================================================
__global__ void __launch_bounds__(256) topk_kernel(float* __restrict__ aux_out, int write_aux) {
    __shared__ unsigned s_ckey[CAP];
    __shared__ int      s_cidx[CAP];
    __shared__ int      s_ccount;
    __shared__ unsigned s_wcnt[8][16];
    __shared__ unsigned s_cnt[16];

    int col = blockIdx.x;
    int b = col >> 10, j = col & 1023;
    int tid = threadIdx.x;
    int lane = tid & 31, wid = tid >> 5;
    if (tid == 0) s_ccount = 0;

    const uint4* __restrict__ src = (const uint4*)(&g_qkT[b][j][0]);

    unsigned maskhi = 0, prefix = 0;
    int krem = K_;

    for (int shift = 28; shift >= 0; shift -= 4) {
        // nibble histogram of elements matching current prefix,
        // packed 8-bit counters in two uint64 (max 64 counts/thread)
        unsigned long long acc0 = 0, acc1 = 0;
        #pragma unroll
        for (int k = 0; k < 16; k++) {
            uint4 v = src[tid + 256 * k];
            #pragma unroll
            for (int e = 0; e < 4; e++) {
                unsigned key = (e == 0) ? v.x : (e == 1) ? v.y : (e == 2) ? v.z : v.w;
                if ((key & maskhi) == prefix) {
                    int nib = (key >> shift) & 15;
                    if (nib < 8) acc0 += 1ull << (nib * 8);
                    else         acc1 += 1ull << ((nib - 8) * 8);
                }
            }
        }
        unsigned cnt[16];
        #pragma unroll
        for (int n2 = 0; n2 < 8; n2++) {
            cnt[n2]     = (unsigned)((acc0 >> (n2 * 8)) & 0xff);
            cnt[n2 + 8] = (unsigned)((acc1 >> (n2 * 8)) & 0xff);
        }
        #pragma unroll
        for (int n2 = 0; n2 < 16; n2++) {
            #pragma unroll
            for (int o = 16; o; o >>= 1)
                cnt[n2] += __shfl_xor_sync(0xffffffffu, cnt[n2], o);
        }
        __syncthreads();   // prior-pass consumers of s_wcnt/s_cnt done
        if (lane == 0) {
            #pragma unroll
            for (int n2 = 0; n2 < 16; n2++) s_wcnt[wid][n2] = cnt[n2];
        }
        __syncthreads();
        if (tid < 16) {
            unsigned s = 0;
            #pragma unroll
            for (int w = 0; w < 8; w++) s += s_wcnt[w][tid];
            s_cnt[tid] = s;
        }
        __syncthreads();

        // uniform: pick bucket containing the krem-th largest
        int cum = 0, nibSel = 0;
        for (int n2 = 15; n2 >= 0; n2--) {
            int c = (int)s_cnt[n2];
            if (cum + c >= krem) { nibSel = n2; break; }
            cum += c;
        }
        krem -= cum;
        prefix |= ((unsigned)nibSel) << shift;
        maskhi |= 0xFu << shift;
        int total = (K_ - krem) + (int)s_cnt[nibSel];
        if (total <= THRESH || shift == 0) break;
    }

    __syncthreads();

    // compact all elements with key >= prefix (prefix low bits are 0,
    // so masked-compare == plain unsigned compare). qualify rate is
    // ~C/16384 < 1% -> rare smem atomics.
    #pragma unroll
    for (int k = 0; k < 16; k++) {
        uint4 v = src[tid + 256 * k];
        int base = (tid + 256 * k) * 4;
        if (v.x >= prefix) { int p = atomicAdd(&s_ccount, 1); if (p < CAP) { s_ckey[p] = v.x; s_cidx[p] = base;     } }
        if (v.y >= prefix) { int p = atomicAdd(&s_ccount, 1); if (p < CAP) { s_ckey[p] = v.y; s_cidx[p] = base + 1; } }
        if (v.z >= prefix) { int p = atomicAdd(&s_ccount, 1); if (p < CAP) { s_ckey[p] = v.z; s_cidx[p] = base + 2; } }
        if (v.w >= prefix) { int p = atomicAdd(&s_ccount, 1); if (p < CAP) { s_ckey[p] = v.w; s_cidx[p] = base + 3; } }
    }
    __syncthreads();

    int C = s_ccount < CAP ? s_ccount : CAP;

    // exact rank among candidates; rank r < 32 => r-th largest
    for (int i = tid; i < C; i += 256) {
        unsigned ki = s_ckey[i];
        int      ii = s_cidx[i];
        int rank = 0;
        for (int jc = 0; jc < C; jc++) {
            unsigned kj = s_ckey[jc];
            int      ij = s_cidx[jc];
            rank += (kj > ki) || (kj == ki && ij < ii);
        }
        if (rank < K_) {
            g_sel[b][j][rank] = ii;
            if (write_aux && rank < KK) {
                int o = (b * HWREF + j) * KK + rank;
                aux_out[MEMOUT_ELEMS + o]                   = (float)ii;
                aux_out[MEMOUT_ELEMS + B_ * HWREF * KK + o] = ord2f(ki);
            }
        }
    }
}

// ============================================================
// Kernel 3: sparse block attention
// ============================================================
__global__ void attn_kernel(const float* __restrict__ q_in, float* __restrict__ out) {
    __shared__ float4 q_s4[4][32];
    __shared__ float4 p_s[128];
    __shared__ int    sel[K_];

    int blk = blockIdx.x;
    int b  = blk >> 10, jq = blk & 1023;
    int hr = jq >> 5,   wr = jq & 31;
    int tid = threadIdx.x;

    if (tid < K_) sel[tid] = g_sel[b][jq][tid];
    if (tid < DE) {
        int c = tid;
        const float* qp = q_in + ((b * DE + c) * H_ + hr * 2) * W_ + wr * 2;
        float2 r0 = *(const float2*)qp;
        float2 r1 = *(const float2*)(qp + W_);
        ((float*)q_s4)[0 * DE + c] = r0.x;
        ((float*)q_s4)[1 * DE + c] = r0.y;
        ((float*)q_s4)[2 * DE + c] = r1.x;
        ((float*)q_s4)[3 * DE + c] = r1.y;
    }
    __syncthreads();

    int wid = tid >> 5, lane = tid & 31;
    float4 q0 = q_s4[0][lane];
    float4 q1 = q_s4[1][lane];
    float4 q2 = q_s4[2][lane];
    float4 q3 = q_s4[3][lane];
    const float scale = 0.08838834764831845f;  // 1/sqrt(128)

    #pragma unroll 4
    for (int mm = 0; mm < 16; mm++) {
        int m  = wid * 16 + mm;
        int ks = m >> 2, pm = m & 3;
        int n  = sel[ks];
        const float4* kp = (const float4*)(&g_mb_in[b][n][pm][0]);
        float4 kv = kp[lane];
        float a0 = kv.x*q0.x + kv.y*q0.y + kv.z*q0.z + kv.w*q0.w;
        float a1 = kv.x*q1.x + kv.y*q1.y + kv.z*q1.z + kv.w*q1.w;
        float a2 = kv.x*q2.x + kv.y*q2.y + kv.z*q2.z + kv.w*q2.w;
        float a3 = kv.x*q3.x + kv.y*q3.y + kv.z*q3.z + kv.w*q3.w;
        #pragma unroll
        for (int o = 16; o; o >>= 1) {
            a0 += __shfl_xor_sync(0xffffffffu, a0, o);
            a1 += __shfl_xor_sync(0xffffffffu, a1, o);
            a2 += __shfl_xor_sync(0xffffffffu, a2, o);
            a3 += __shfl_xor_sync(0xffffffffu, a3, o);
        }
        if (lane == 0)
            p_s[m] = make_float4(a0 * scale, a1 * scale, a2 * scale, a3 * scale);
    }
    __syncthreads();

    if (wid < 4) {
        int p = wid;
        float* ps = (float*)p_s;
        float x0 = ps[(lane      ) * 4 + p];
        float x1 = ps[(lane + 32 ) * 4 + p];
        float x2 = ps[(lane + 64 ) * 4 + p];
        float x3 = ps[(lane + 96 ) * 4 + p];
        float mx = fmaxf(fmaxf(x0, x1), fmaxf(x2, x3));
        #pragma unroll
        for (int o = 16; o; o >>= 1) mx = fmaxf(mx, __shfl_xor_sync(0xffffffffu, mx, o));
        float e0 = __expf(x0 - mx), e1 = __expf(x1 - mx);
        float e2 = __expf(x2 - mx), e3 = __expf(x3 - mx);
        float sm = e0 + e1 + e2 + e3;
        #pragma unroll
        for (int o = 16; o; o >>= 1) sm += __shfl_xor_sync(0xffffffffu, sm, o);
        float inv = 1.0f / sm;
        ps[(lane      ) * 4 + p] = e0 * inv;
        ps[(lane + 32 ) * 4 + p] = e1 * inv;
        ps[(lane + 64 ) * 4 + p] = e2 * inv;
        ps[(lane + 96 ) * 4 + p] = e3 * inv;
    }
    __syncthreads();

    int c = tid;
    float a0 = 0.f, a1 = 0.f, a2 = 0.f, a3 = 0.f;
    #pragma unroll 4
    for (int ks = 0; ks < K_; ks++) {
        int n = sel[ks];
        const float* vbase = &g_mb_out[b][n][0][0];
        #pragma unroll
        for (int pm = 0; pm < 4; pm++) {
            float  v  = vbase[pm * DOo + c];
            float4 pw = p_s[ks * 4 + pm];
            a0 += v * pw.x; a1 += v * pw.y; a2 += v * pw.z; a3 += v * pw.w;
        }
    }
    float* ob = out + ((b * DOo + c) * H_ + hr * 2) * W_ + wr * 2;
    *(float2*)ob        = make_float2(a0, a1);
    *(float2*)(ob + W_) = make_float2(a2, a3);
}

// ============================================================
extern "C" void kernel_launch(void* const* d_in, const int* in_sizes, int n_in,
                              void* d_out, int out_size) {
    const float* m_in  = (const float*)d_in[0];
    const float* m_out = (const float*)d_in[1];
    const float* q_in  = (const float*)d_in[2];
    const float* qk    = (const float*)d_in[3];
    float* out = (float*)d_out;

    int write_aux = (out_size >= MEMOUT_ELEMS + 2 * B_ * HWREF * KK) ? 1 : 0;

    dim3 tb(32, 8);
    blockify_kernel<<<16384, tb>>>(m_in, DE, 0);
    blockify_kernel<<<32768, tb>>>(m_out, DOo, 1);
    qk_transpose_kernel<<<32768, tb>>>(qk);
    topk_kernel<<<B_ * HWREF, 256>>>(out, write_aux);
    attn_kernel<<<B_ * HWREF, 256>>>(q_in, out);
}

// round 7
// speedup vs baseline: 1.6582x; 1.1657x over previous
#include <cuda_runtime.h>

#define B_ 2
#define DE 128
#define DOo 256
#define T_ 16
#define H_ 64
#define W_ 64
#define NBLK 16384   // T * 32 * 32
#define HWREF 1024   // 32 * 32
#define K_ 32
#define KK 8
#define RCAP 1536
#define CANDCAP 1024
#define QTHRESH 2.0f
#define MEMOUT_ELEMS (B_*DOo*H_*W_)   // 2097152

// ---- scratch (static device globals; no runtime allocation) ----
__device__ float    g_mb_in[B_][NBLK][4][DE];    // [b][block][px][c]
__device__ float    g_mb_out[B_][NBLK][4][DOo];
__device__ unsigned g_ccount[B_][HWREF];
__device__ uint2    g_cand[B_][HWREF][CANDCAP];  // (ordered key, block idx)
__device__ int      g_sel[B_][HWREF][K_];        // selected blocks (desc-value order)

__device__ __forceinline__ unsigned f2ord(float f) {
    unsigned u = __float_as_uint(f);
    return (u & 0x80000000u) ? ~u : (u | 0x80000000u);
}
__device__ __forceinline__ float ord2f(unsigned k) {
    unsigned u = (k & 0x80000000u) ? (k & 0x7fffffffu) : ~k;
    return __uint_as_float(u);
}

// ============================================================
// Kernel 0: blockify  m[b][c][t][h][w] -> mb[b][n][pm][c]
// ============================================================
__global__ void blockify_kernel(const float* __restrict__ in, int D, int is_out) {
    __shared__ float tile[32][33];
    float* out = is_out ? &g_mb_out[0][0][0][0] : &g_mb_in[0][0][0][0];
    int bx = blockIdx.x;
    int wt = bx & 1;  bx >>= 1;
    int h  = bx & 63; bx >>= 6;
    int t  = bx & 15; bx >>= 4;
    int nct = D >> 5;
    int ct = bx % nct;
    int b  = bx / nct;
    int tx = threadIdx.x, ty = threadIdx.y;
    #pragma unroll
    for (int r = 0; r < 4; r++) {
        int c = (ct << 5) + ty + (r << 3);
        tile[ty + (r << 3)][tx] =
            in[(((b * D + c) * T_ + t) * H_ + h) * W_ + (wt << 5) + tx];
    }
    __syncthreads();
    int hr = h >> 1, im = h & 1;
    #pragma unroll
    for (int r = 0; r < 4; r++) {
        int wi = ty + (r << 3);
        int w  = (wt << 5) + wi;
        int wr = w >> 1, jm = w & 1;
        int n  = t * 1024 + hr * 32 + wr;
        int pm = im * 2 + jm;
        out[((b * NBLK + n) * 4 + pm) * D + (ct << 5) + tx] = tile[tx][wi];
    }
}

// ============================================================
// Kernel 1a: zero the per-column candidate counters (graph replay
// safe: state reset every launch)
// ============================================================
__global__ void zero_counts_kernel() {
    int t = blockIdx.x * 256 + threadIdx.x;
    if (t < B_ * HWREF) ((unsigned*)g_ccount)[t] = 0;
}

// ============================================================
// Kernel 1b: single coalesced pass over qk in ORIGINAL layout.
// Compacts all elements >= QTHRESH (~2.3% of N(0,1)) into
// per-column candidate buffers. Replaces the transpose + full
// radix scans entirely.
// ============================================================
__global__ void __launch_bounds__(256) qk_scatter_kernel(const float* __restrict__ qk) {
    size_t lin = ((size_t)blockIdx.x * 256 + threadIdx.x) * 4;
    float4 v = *(const float4*)(qk + lin);
    unsigned bn = (unsigned)(lin >> 10);   // b*NBLK + n
    int j0 = (int)(lin & 1023);
    int b  = bn >> 14;
    int n  = bn & 16383;
    #pragma unroll
    for (int e = 0; e < 4; e++) {
        float val = (e == 0) ? v.x : (e == 1) ? v.y : (e == 2) ? v.z : v.w;
        if (val >= QTHRESH) {
            int j = j0 + e;
            unsigned p = atomicAdd(&g_ccount[b][j], 1u);
            if (p < CANDCAP) g_cand[b][j][p] = make_uint2(f2ord(val), (unsigned)n);
        }
    }
}

// ============================================================
// Kernel 2: per-column exact top-32 refine. One CTA per (b,j).
// Main path: ~373 candidates from g_cand into smem; nibble-radix
// narrow until qualifying count <= 128; compact; exact pairwise
// rank (desc value, ties -> lower index == jax.lax.top_k order).
// Fallback (count < 32 or > CANDCAP; never taken on bench data):
// exact radix select over the strided column from qk directly.
// ============================================================
__global__ void __launch_bounds__(256) topk_refine_kernel(const float* __restrict__ qk,
                                                          float* __restrict__ aux_out,
                                                          int write_aux) {
    __shared__ unsigned s_key[RCAP];
    __shared__ int      s_idx[RCAP];
    __shared__ unsigned s_k2[RCAP];
    __shared__ int      s_i2[RCAP];
    __shared__ int      s_c;
    __shared__ unsigned s_hist[16];

    int col = blockIdx.x;
    int b = col >> 10, j = col & 1023;
    int tid = threadIdx.x;

    unsigned maskhi = 0, prefix = 0;
    int krem = K_;
    int shift = 28;
    int cnt, total;

    int C = (int)g_ccount[b][j];
    if (C >= K_ && C <= CANDCAP) {
        // ---- main path ----
        for (int i = tid; i < C; i += 256) {
            uint2 c = g_cand[b][j][i];
            s_key[i] = c.x;
            s_idx[i] = (int)c.y;
        }
        cnt = C;
        total = C;
        __syncthreads();
    } else {
        // ---- fallback: exact radix over the strided column ----
        const float* colp = qk + (size_t)b * NBLK * HWREF + j;
        total = NBLK;
        for (; shift >= 0 && total > CANDCAP; shift -= 4) {
            if (tid < 16) s_hist[tid] = 0;
            __syncthreads();
            for (int i = tid; i < NBLK; i += 256) {
                unsigned key = f2ord(colp[(size_t)i * HWREF]);
                if ((key & maskhi) == prefix)
                    atomicAdd(&s_hist[(key >> shift) & 15], 1u);
            }
            __syncthreads();
            int cum = 0, nib = 0;
            for (int n2 = 15; n2 >= 0; n2--) {
                int c = (int)s_hist[n2];
                if (cum + c >= krem) { nib = n2; break; }
                cum += c;
            }
            krem -= cum;
            prefix |= (unsigned)nib << shift;
            maskhi |= 0xFu << shift;
            total = (K_ - krem) + (int)s_hist[nib];
            __syncthreads();
        }
        if (tid == 0) s_c = 0;
        __syncthreads();
        for (int i = tid; i < NBLK; i += 256) {
            unsigned key = f2ord(colp[(size_t)i * HWREF]);
            if (key >= prefix) {
                int p = atomicAdd(&s_c, 1);
                if (p < RCAP) { s_key[p] = key; s_idx[p] = i; }
            }
        }
        __syncthreads();
        cnt = s_c < RCAP ? s_c : RCAP;
        total = cnt;
        __syncthreads();
    }

    // ---- common: narrow candidate set until qualifying <= 128 ----
    for (; shift >= 0 && total > 128; shift -= 4) {
        if (tid < 16) s_hist[tid] = 0;
        __syncthreads();
        for (int i = tid; i < cnt; i += 256) {
            unsigned key = s_key[i];
            if ((key & maskhi) == prefix)
                atomicAdd(&s_hist[(key >> shift) & 15], 1u);
        }
        __syncthreads();
        int cum = 0, nib = 0;
        for (int n2 = 15; n2 >= 0; n2--) {
            int c = (int)s_hist[n2];
            if (cum + c >= krem) { nib = n2; break; }
            cum += c;
        }
        krem -= cum;
        prefix |= (unsigned)nib << shift;
        maskhi |= 0xFu << shift;
        total = (K_ - krem) + (int)s_hist[nib];
        __syncthreads();
    }

    // ---- compact qualifying (key >= prefix; prefix low bits are 0) ----
    if (tid == 0) s_c = 0;
    __syncthreads();
    for (int i = tid; i < cnt; i += 256) {
        unsigned key = s_key[i];
        if (key >= prefix) {
            int p = atomicAdd(&s_c, 1);
            if (p < RCAP) { s_k2[p] = key; s_i2[p] = s_idx[i]; }
        }
    }
    __syncthreads();
    int C2 = s_c < RCAP ? s_c : RCAP;

    // ---- exact rank; rank r < 32 => r-th largest ----
    for (int i = tid; i < C2; i += 256) {
        unsigned ki = s_k2[i];
        int      ii = s_i2[i];
        int rank = 0;
        for (int jc = 0; jc < C2; jc++) {
            unsigned kj = s_k2[jc];
            rank += (kj > ki) || (kj == ki && s_i2[jc] < ii);
        }
        if (rank < K_) {
            g_sel[b][j][rank] = ii;
            if (write_aux && rank < KK) {
                int o = (b * HWREF + j) * KK + rank;
                aux_out[MEMOUT_ELEMS + o]                   = (float)ii;
                aux_out[MEMOUT_ELEMS + B_ * HWREF * KK + o] = ord2f(ki);
            }
        }
    }
}

// ============================================================
// Kernel 3: sparse block attention
// ============================================================
__global__ void attn_kernel(const float* __restrict__ q_in, float* __restrict__ out) {
    __shared__ float4 q_s4[4][32];
    __shared__ float4 p_s[128];
    __shared__ int    sel[K_];

    int blk = blockIdx.x;
    int b  = blk >> 10, jq = blk & 1023;
    int hr = jq >> 5,   wr = jq & 31;
    int tid = threadIdx.x;

    if (tid < K_) sel[tid] = g_sel[b][jq][tid];
    if (tid < DE) {
        int c = tid;
        const float* qp = q_in + ((b * DE + c) * H_ + hr * 2) * W_ + wr * 2;
        float2 r0 = *(const float2*)qp;
        float2 r1 = *(const float2*)(qp + W_);
        ((float*)q_s4)[0 * DE + c] = r0.x;
        ((float*)q_s4)[1 * DE + c] = r0.y;
        ((float*)q_s4)[2 * DE + c] = r1.x;
        ((float*)q_s4)[3 * DE + c] = r1.y;
    }
    __syncthreads();

    int wid = tid >> 5, lane = tid & 31;
    float4 q0 = q_s4[0][lane];
    float4 q1 = q_s4[1][lane];
    float4 q2 = q_s4[2][lane];
    float4 q3 = q_s4[3][lane];
    const float scale = 0.08838834764831845f;  // 1/sqrt(128)

    #pragma unroll 4
    for (int mm = 0; mm < 16; mm++) {
        int m  = wid * 16 + mm;
        int ks = m >> 2, pm = m & 3;
        int n  = sel[ks];
        const float4* kp = (const float4*)(&g_mb_in[b][n][pm][0]);
        float4 kv = kp[lane];
        float a0 = kv.x*q0.x + kv.y*q0.y + kv.z*q0.z + kv.w*q0.w;
        float a1 = kv.x*q1.x + kv.y*q1.y + kv.z*q1.z + kv.w*q1.w;
        float a2 = kv.x*q2.x + kv.y*q2.y + kv.z*q2.z + kv.w*q2.w;
        float a3 = kv.x*q3.x + kv.y*q3.y + kv.z*q3.z + kv.w*q3.w;
        #pragma unroll
        for (int o = 16; o; o >>= 1) {
            a0 += __shfl_xor_sync(0xffffffffu, a0, o);
            a1 += __shfl_xor_sync(0xffffffffu, a1, o);
            a2 += __shfl_xor_sync(0xffffffffu, a2, o);
            a3 += __shfl_xor_sync(0xffffffffu, a3, o);
        }
        if (lane == 0)
            p_s[m] = make_float4(a0 * scale, a1 * scale, a2 * scale, a3 * scale);
    }
    __syncthreads();

    if (wid < 4) {
        int p = wid;
        float* ps = (float*)p_s;
        float x0 = ps[(lane      ) * 4 + p];
        float x1 = ps[(lane + 32 ) * 4 + p];
        float x2 = ps[(lane + 64 ) * 4 + p];
        float x3 = ps[(lane + 96 ) * 4 + p];
        float mx = fmaxf(fmaxf(x0, x1), fmaxf(x2, x3));
        #pragma unroll
        for (int o = 16; o; o >>= 1) mx = fmaxf(mx, __shfl_xor_sync(0xffffffffu, mx, o));
        float e0 = __expf(x0 - mx), e1 = __expf(x1 - mx);
        float e2 = __expf(x2 - mx), e3 = __expf(x3 - mx);
        float sm = e0 + e1 + e2 + e3;
        #pragma unroll
        for (int o = 16; o; o >>= 1) sm += __shfl_xor_sync(0xffffffffu, sm, o);
        float inv = 1.0f / sm;
        ps[(lane      ) * 4 + p] = e0 * inv;
        ps[(lane + 32 ) * 4 + p] = e1 * inv;
        ps[(lane + 64 ) * 4 + p] = e2 * inv;
        ps[(lane + 96 ) * 4 + p] = e3 * inv;
    }
    __syncthreads();

    int c = tid;
    float a0 = 0.f, a1 = 0.f, a2 = 0.f, a3 = 0.f;
    #pragma unroll 4
    for (int ks = 0; ks < K_; ks++) {
        int n = sel[ks];
        const float* vbase = &g_mb_out[b][n][0][0];
        #pragma unroll
        for (int pm = 0; pm < 4; pm++) {
            float  v  = vbase[pm * DOo + c];
            float4 pw = p_s[ks * 4 + pm];
            a0 += v * pw.x; a1 += v * pw.y; a2 += v * pw.z; a3 += v * pw.w;
        }
    }
    float* ob = out + ((b * DOo + c) * H_ + hr * 2) * W_ + wr * 2;
    *(float2*)ob        = make_float2(a0, a1);
    *(float2*)(ob + W_) = make_float2(a2, a3);
}

// ============================================================
extern "C" void kernel_launch(void* const* d_in, const int* in_sizes, int n_in,
                              void* d_out, int out_size) {
    const float* m_in  = (const float*)d_in[0];
    const float* m_out = (const float*)d_in[1];
    const float* q_in  = (const float*)d_in[2];
    const float* qk    = (const float*)d_in[3];
    float* out = (float*)d_out;

    int write_aux = (out_size >= MEMOUT_ELEMS + 2 * B_ * HWREF * KK) ? 1 : 0;

    dim3 tb(32, 8);
    blockify_kernel<<<16384, tb>>>(m_in, DE, 0);
    blockify_kernel<<<32768, tb>>>(m_out, DOo, 1);
    zero_counts_kernel<<<(B_ * HWREF + 255) / 256, 256>>>();
    // one element per thread-slot: B*NBLK*HWREF / (256*4) CTAs
    qk_scatter_kernel<<<(B_ * NBLK * HWREF) / 1024, 256>>>(qk);
    topk_refine_kernel<<<B_ * HWREF, 256>>>(qk, out, write_aux);
    attn_kernel<<<B_ * HWREF, 256>>>(q_in, out);
}

// round 9
// speedup vs baseline: 1.7184x; 1.0363x over previous
#include <cuda_runtime.h>

#define B_ 2
#define DE 128
#define DOo 256
#define T_ 16
#define H_ 64
#define W_ 64
#define NBLK 16384   // T * 32 * 32
#define HWREF 1024   // 32 * 32
#define K_ 32
#define KK 8
#define RCAP 1536
#define CANDCAP 1024
#define QTHRESH 2.0f
#define MEMOUT_ELEMS (B_*DOo*H_*W_)   // 2097152

// ---- scratch (static device globals; no runtime allocation) ----
__device__ float    g_mb_in[B_][NBLK][4][DE];    // [b][block][px][c]
__device__ float    g_mb_out[B_][NBLK][4][DOo];
__device__ unsigned g_ccount[B_][HWREF];
__device__ uint2    g_cand[B_][HWREF][CANDCAP];  // (ordered key, block idx)
__device__ int      g_sel[B_][HWREF][K_];        // selected blocks (desc-value order)

__device__ __forceinline__ unsigned f2ord(float f) {
    unsigned u = __float_as_uint(f);
    return (u & 0x80000000u) ? ~u : (u | 0x80000000u);
}
__device__ __forceinline__ float ord2f(unsigned k) {
    unsigned u = (k & 0x80000000u) ? (k & 0x7fffffffu) : ~k;
    return __uint_as_float(u);
}

// ============================================================
// Kernel 0: blockify  m[b][c][t][h][w] -> mb[b][n][pm][c]
// ============================================================
__global__ void blockify_kernel(const float* __restrict__ in, int D, int is_out) {
    __shared__ float tile[32][33];
    float* out = is_out ? &g_mb_out[0][0][0][0] : &g_mb_in[0][0][0][0];
    int bx = blockIdx.x;
    int wt = bx & 1;  bx >>= 1;
    int h  = bx & 63; bx >>= 6;
    int t  = bx & 15; bx >>= 4;
    int nct = D >> 5;
    int ct = bx % nct;
    int b  = bx / nct;
    int tx = threadIdx.x, ty = threadIdx.y;
    #pragma unroll
    for (int r = 0; r < 4; r++) {
        int c = (ct << 5) + ty + (r << 3);
        tile[ty + (r << 3)][tx] =
            in[(((b * D + c) * T_ + t) * H_ + h) * W_ + (wt << 5) + tx];
    }
    __syncthreads();
    int hr = h >> 1, im = h & 1;
    #pragma unroll
    for (int r = 0; r < 4; r++) {
        int wi = ty + (r << 3);
        int w  = (wt << 5) + wi;
        int wr = w >> 1, jm = w & 1;
        int n  = t * 1024 + hr * 32 + wr;
        int pm = im * 2 + jm;
        out[((b * NBLK + n) * 4 + pm) * D + (ct << 5) + tx] = tile[tx][wi];
    }
}

// ============================================================
// Kernel 1a: zero the per-column candidate counters
// ============================================================
__global__ void zero_counts_kernel() {
    int t = blockIdx.x * 256 + threadIdx.x;
    if (t < B_ * HWREF) ((unsigned*)g_ccount)[t] = 0;
}

// ============================================================
// Kernel 1b: single coalesced pass over qk in ORIGINAL layout,
// 8 independent float4 loads per thread (MLP=8 -> hides DRAM
// latency; R7 version had MLP=1 and ran at 24% of HBM).
// Compacts all elements >= QTHRESH (~2.3% of N(0,1)) into
// per-column candidate buffers.
// ============================================================
__global__ void __launch_bounds__(256) qk_scatter_kernel(const float* __restrict__ qk) {
    const float4* __restrict__ src = (const float4*)qk;
    int base = blockIdx.x * (256 * 8) + threadIdx.x;
    float4 v[8];
    #pragma unroll
    for (int k = 0; k < 8; k++) v[k] = src[base + k * 256];
    #pragma unroll
    for (int k = 0; k < 8; k++) {
        // quick reject: vast majority of float4s have no qualifier
        if (v[k].x < QTHRESH && v[k].y < QTHRESH &&
            v[k].z < QTHRESH && v[k].w < QTHRESH) continue;
        int f   = base + k * 256;      // float4 linear index
        int lin = f * 4;               // element index (fits in int: max 33.5M)
        int j0  = lin & 1023;
        unsigned bn = ((unsigned)lin) >> 10;   // b*NBLK + n
        int b = bn >> 14;
        int n = bn & 16383;
        #pragma unroll
        for (int e = 0; e < 4; e++) {
            float val = (e == 0) ? v[k].x : (e == 1) ? v[k].y : (e == 2) ? v[k].z : v[k].w;
            if (val >= QTHRESH) {
                int j = j0 + e;
                unsigned p = atomicAdd(&g_ccount[b][j], 1u);
                if (p < CANDCAP) g_cand[b][j][p] = make_uint2(f2ord(val), (unsigned)n);
            }
        }
    }
}

// ============================================================
// Kernel 2: per-column exact top-32 refine. One CTA per (b,j).
// Main path: candidates from g_cand into smem; nibble-radix narrow
// until qualifying count <= 128; compact; exact pairwise rank
// (desc value, ties -> lower index == jax.lax.top_k order).
// Fallback (count < 32 or > CANDCAP; never taken on bench data):
// exact radix select over the strided column from qk directly.
// ============================================================
__global__ void __launch_bounds__(256) topk_refine_kernel(const float* __restrict__ qk,
                                                          float* __restrict__ aux_out,
                                                          int write_aux) {
    __shared__ unsigned s_key[RCAP];
    __shared__ int      s_idx[RCAP];
    __shared__ unsigned s_k2[RCAP];
    __shared__ int      s_i2[RCAP];
    __shared__ int      s_c;
    __shared__ unsigned s_hist[16];

    int col = blockIdx.x;
    int b = col >> 10, j = col & 1023;
    int tid = threadIdx.x;

    unsigned maskhi = 0, prefix = 0;
    int krem = K_;
    int shift = 28;
    int cnt, total;

    int C = (int)g_ccount[b][j];
    if (C >= K_ && C <= CANDCAP) {
        for (int i = tid; i < C; i += 256) {
            uint2 c = g_cand[b][j][i];
            s_key[i] = c.x;
            s_idx[i] = (int)c.y;
        }
        cnt = C;
        total = C;
        __syncthreads();
    } else {
        const float* colp = qk + (size_t)b * NBLK * HWREF + j;
        total = NBLK;
        for (; shift >= 0 && total > CANDCAP; shift -= 4) {
            if (tid < 16) s_hist[tid] = 0;
            __syncthreads();
            for (int i = tid; i < NBLK; i += 256) {
                unsigned key = f2ord(colp[(size_t)i * HWREF]);
                if ((key & maskhi) == prefix)
                    atomicAdd(&s_hist[(key >> shift) & 15], 1u);
            }
            __syncthreads();
            int cum = 0, nib = 0;
            for (int n2 = 15; n2 >= 0; n2--) {
                int c = (int)s_hist[n2];
                if (cum + c >= krem) { nib = n2; break; }
                cum += c;
            }
            krem -= cum;
            prefix |= (unsigned)nib << shift;
            maskhi |= 0xFu << shift;
            total = (K_ - krem) + (int)s_hist[nib];
            __syncthreads();
        }
        if (tid == 0) s_c = 0;
        __syncthreads();
        for (int i = tid; i < NBLK; i += 256) {
            unsigned key = f2ord(colp[(size_t)i * HWREF]);
            if (key >= prefix) {
                int p = atomicAdd(&s_c, 1);
                if (p < RCAP) { s_key[p] = key; s_idx[p] = i; }
            }
        }
        __syncthreads();
        cnt = s_c < RCAP ? s_c : RCAP;
        total = cnt;
        __syncthreads();
    }

    // narrow candidate set until qualifying <= 128
    for (; shift >= 0 && total > 128; shift -= 4) {
        if (tid < 16) s_hist[tid] = 0;
        __syncthreads();
        for (int i = tid; i < cnt; i += 256) {
            unsigned key = s_key[i];
            if ((key & maskhi) == prefix)
                atomicAdd(&s_hist[(key >> shift) & 15], 1u);
        }
        __syncthreads();
        int cum = 0, nib = 0;
        for (int n2 = 15; n2 >= 0; n2--) {
            int c = (int)s_hist[n2];
            if (cum + c >= krem) { nib = n2; break; }
            cum += c;
        }
        krem -= cum;
        prefix |= (unsigned)nib << shift;
        maskhi |= 0xFu << shift;
        total = (K_ - krem) + (int)s_hist[nib];
        __syncthreads();
    }

    // compact qualifying (key >= prefix; prefix low bits are 0)
    if (tid == 0) s_c = 0;
    __syncthreads();
    for (int i = tid; i < cnt; i += 256) {
        unsigned key = s_key[i];
        if (key >= prefix) {
            int p = atomicAdd(&s_c, 1);
            if (p < RCAP) { s_k2[p] = key; s_i2[p] = s_idx[i]; }
        }
    }
    __syncthreads();
    int C2 = s_c < RCAP ? s_c : RCAP;

    // exact rank; rank r < 32 => r-th largest
    for (int i = tid; i < C2; i += 256) {
        unsigned ki = s_k2[i];
        int      ii = s_i2[i];
        int rank = 0;
        for (int jc = 0; jc < C2; jc++) {
            unsigned kj = s_k2[jc];
            rank += (kj > ki) || (kj == ki && s_i2[jc] < ii);
        }
        if (rank < K_) {
            g_sel[b][j][rank] = ii;
            if (write_aux && rank < KK) {
                int o = (b * HWREF + j) * KK + rank;
                aux_out[MEMOUT_ELEMS + o]                   = (float)ii;
                aux_out[MEMOUT_ELEMS + B_ * HWREF * KK + o] = ord2f(ki);
            }
        }
    }
}

// ============================================================
// Kernel 3: sparse block attention
// ============================================================
__global__ void attn_kernel(const float* __restrict__ q_in, float* __restrict__ out) {
    __shared__ float4 q_s4[4][32];
    __shared__ float4 p_s[128];
    __shared__ int    sel[K_];

    int blk = blockIdx.x;
    int b  = blk >> 10, jq = blk & 1023;
    int hr = jq >> 5,   wr = jq & 31;
    int tid = threadIdx.x;

    if (tid < K_) sel[tid] = g_sel[b][jq][tid];
    if (tid < DE) {
        int c = tid;
        const float* qp = q_in + ((b * DE + c) * H_ + hr * 2) * W_ + wr * 2;
        float2 r0 = *(const float2*)qp;
        float2 r1 = *(const float2*)(qp + W_);
        ((float*)q_s4)[0 * DE + c] = r0.x;
        ((float*)q_s4)[1 * DE + c] = r0.y;
        ((float*)q_s4)[2 * DE + c] = r1.x;
        ((float*)q_s4)[3 * DE + c] = r1.y;
    }
    __syncthreads();

    int wid = tid >> 5, lane = tid & 31;
    float4 q0 = q_s4[0][lane];
    float4 q1 = q_s4[1][lane];
    float4 q2 = q_s4[2][lane];
    float4 q3 = q_s4[3][lane];
    const float scale = 0.08838834764831845f;  // 1/sqrt(128)

    #pragma unroll 4
    for (int mm = 0; mm < 16; mm++) {
        int m  = wid * 16 + mm;
        int ks = m >> 2, pm = m & 3;
        int n  = sel[ks];
        const float4* kp = (const float4*)(&g_mb_in[b][n][pm][0]);
        float4 kv = kp[lane];
        float a0 = kv.x*q0.x + kv.y*q0.y + kv.z*q0.z + kv.w*q0.w;
        float a1 = kv.x*q1.x + kv.y*q1.y + kv.z*q1.z + kv.w*q1.w;
        float a2 = kv.x*q2.x + kv.y*q2.y + kv.z*q2.z + kv.w*q2.w;
        float a3 = kv.x*q3.x + kv.y*q3.y + kv.z*q3.z + kv.w*q3.w;
        #pragma unroll
        for (int o = 16; o; o >>= 1) {
            a0 += __shfl_xor_sync(0xffffffffu, a0, o);
            a1 += __shfl_xor_sync(0xffffffffu, a1, o);
            a2 += __shfl_xor_sync(0xffffffffu, a2, o);
            a3 += __shfl_xor_sync(0xffffffffu, a3, o);
        }
        if (lane == 0)
            p_s[m] = make_float4(a0 * scale, a1 * scale, a2 * scale, a3 * scale);
    }
    __syncthreads();

    if (wid < 4) {
        int p = wid;
        float* ps = (float*)p_s;
        float x0 = ps[(lane      ) * 4 + p];
        float x1 = ps[(lane + 32 ) * 4 + p];
        float x2 = ps[(lane + 64 ) * 4 + p];
        float x3 = ps[(lane + 96 ) * 4 + p];
        float mx = fmaxf(fmaxf(x0, x1), fmaxf(x2, x3));
        #pragma unroll
        for (int o = 16; o; o >>= 1) mx = fmaxf(mx, __shfl_xor_sync(0xffffffffu, mx, o));
        float e0 = __expf(x0 - mx), e1 = __expf(x1 - mx);
        float e2 = __expf(x2 - mx), e3 = __expf(x3 - mx);
        float sm = e0 + e1 + e2 + e3;
        #pragma unroll
        for (int o = 16; o; o >>= 1) sm += __shfl_xor_sync(0xffffffffu, sm, o);
        float inv = 1.0f / sm;
        ps[(lane      ) * 4 + p] = e0 * inv;
        ps[(lane + 32 ) * 4 + p] = e1 * inv;
        ps[(lane + 64 ) * 4 + p] = e2 * inv;
        ps[(lane + 96 ) * 4 + p] = e3 * inv;
    }
    __syncthreads();

    int c = tid;
    float a0 = 0.f, a1 = 0.f, a2 = 0.f, a3 = 0.f;
    #pragma unroll 4
    for (int ks = 0; ks < K_; ks++) {
        int n = sel[ks];
        const float* vbase = &g_mb_out[b][n][0][0];
        #pragma unroll
        for (int pm = 0; pm < 4; pm++) {
            float  v  = vbase[pm * DOo + c];
            float4 pw = p_s[ks * 4 + pm];
            a0 += v * pw.x; a1 += v * pw.y; a2 += v * pw.z; a3 += v * pw.w;
        }
    }
    float* ob = out + ((b * DOo + c) * H_ + hr * 2) * W_ + wr * 2;
    *(float2*)ob        = make_float2(a0, a1);
    *(float2*)(ob + W_) = make_float2(a2, a3);
}

// ============================================================
extern "C" void kernel_launch(void* const* d_in, const int* in_sizes, int n_in,
                              void* d_out, int out_size) {
    const float* m_in  = (const float*)d_in[0];
    const float* m_out = (const float*)d_in[1];
    const float* q_in  = (const float*)d_in[2];
    const float* qk    = (const float*)d_in[3];
    float* out = (float*)d_out;

    int write_aux = (out_size >= MEMOUT_ELEMS + 2 * B_ * HWREF * KK) ? 1 : 0;

    // Fork a side stream for the topk chain (reads qk only) so it
    // overlaps with the blockify chain (reads m_in/m_out). Created
    // fresh per call (host-side objects only; kernel_launch runs
    // twice total — correctness + capture). Event fork/join keeps
    // the captured graph a single connected DAG.
    cudaStream_t s2;
    cudaEvent_t eFork, eJoin;
    cudaStreamCreateWithFlags(&s2, cudaStreamNonBlocking);
    cudaEventCreateWithFlags(&eFork, cudaEventDisableTiming);
    cudaEventCreateWithFlags(&eJoin, cudaEventDisableTiming);

    cudaEventRecord(eFork, 0);
    cudaStreamWaitEvent(s2, eFork, 0);

    // side branch: topk chain
    zero_counts_kernel<<<(B_ * HWREF + 255) / 256, 256, 0, s2>>>();
    qk_scatter_kernel<<<(B_ * NBLK * HWREF) / (1024 * 8), 256, 0, s2>>>(qk);
    topk_refine_kernel<<<B_ * HWREF, 256, 0, s2>>>(qk, out, write_aux);
    cudaEventRecord(eJoin, s2);

    // main branch: blockify chain
    dim3 tb(32, 8);
    blockify_kernel<<<16384, tb>>>(m_in, DE, 0);
    blockify_kernel<<<32768, tb>>>(m_out, DOo, 1);

    // join + attention
    cudaStreamWaitEvent(0, eJoin, 0);
    attn_kernel<<<B_ * HWREF, 256>>>(q_in, out);
}

// round 14
// speedup vs baseline: 1.8874x; 1.0983x over previous
#include <cuda_runtime.h>
#include <cuda_fp16.h>

#define B_ 2
#define DE 128
#define DOo 256
#define T_ 16
#define H_ 64
#define W_ 64
#define NBLK 16384   // T * 32 * 32
#define HWREF 1024   // 32 * 32
#define K_ 32
#define KK 8
#define RCAP 1536
#define CANDCAP 1024
#define QTHRESH 2.0f
#define MEMOUT_ELEMS (B_*DOo*H_*W_)   // 2097152

// ---- scratch (static device globals; no runtime allocation) ----
// fp16 blockified K/V: total 100 MB -> fits L2 (126 MB) during attn.
__device__ __half   g_mb_in[B_][NBLK][4][DE];    // 33.5 MB [b][block][px][c]
__device__ __half   g_mb_out[B_][NBLK][4][DOo];  // 67 MB
__device__ unsigned g_ccount[B_][HWREF];
__device__ uint2    g_cand[B_][HWREF][CANDCAP];  // (ordered key, block idx)
__device__ int      g_sel[B_][HWREF][K_];        // selected blocks (desc-value order)

__device__ __forceinline__ unsigned f2ord(float f) {
    unsigned u = __float_as_uint(f);
    return (u & 0x80000000u) ? ~u : (u | 0x80000000u);
}
__device__ __forceinline__ float ord2f(unsigned k) {
    unsigned u = (k & 0x80000000u) ? (k & 0x7fffffffu) : ~k;
    return __uint_as_float(u);
}

// ============================================================
// Kernel 0: blockify  m[b][c][t][h][w] -> mb[b][n][pm][c] (fp16)
//   n = t*1024 + (h/2)*32 + (w/2),  pm = (h%2)*2 + (w%2)
// 32(c) x 32(w) smem tile; coalesced fp32 reads, half2 writes.
// Store mapping (bijective, 256 thr x 2 iters = 512 half2 slots):
//   a  = tx & 15                 -> channel pair (16)
//   wi = (tx>>4)|(ty<<1)|(r<<4)  -> w within half-row (32), in [0,31]
// ============================================================
__global__ void blockify_kernel(const float* __restrict__ in, int D, int is_out) {
    __shared__ float tile[32][33];
    __half* out = is_out ? &g_mb_out[0][0][0][0] : &g_mb_in[0][0][0][0];
    int bx = blockIdx.x;
    int wt = bx & 1;  bx >>= 1;
    int h  = bx & 63; bx >>= 6;
    int t  = bx & 15; bx >>= 4;
    int nct = D >> 5;
    int ct = bx % nct;
    int b  = bx / nct;
    int tx = threadIdx.x, ty = threadIdx.y;
    #pragma unroll
    for (int r = 0; r < 4; r++) {
        int c = (ct << 5) + ty + (r << 3);
        tile[ty + (r << 3)][tx] =
            in[(((b * D + c) * T_ + t) * H_ + h) * W_ + (wt << 5) + tx];
    }
    __syncthreads();
    int hr = h >> 1, im = h & 1;
    int a = tx & 15;
    #pragma unroll
    for (int r = 0; r < 2; r++) {
        int wi = (tx >> 4) | (ty << 1) | (r << 4);   // 0..31, bijective
        int w  = (wt << 5) + wi;
        int wr = w >> 1, jm = w & 1;
        int n  = t * 1024 + hr * 32 + wr;
        int pm = im * 2 + jm;
        __half2 hv = __floats2half2_rn(tile[2 * a][wi], tile[2 * a + 1][wi]);
        *(__half2*)(out + (size_t)((b * NBLK + n) * 4 + pm) * D + (ct << 5) + 2 * a) = hv;
    }
}

// ============================================================
// Kernel 1a: zero the per-column candidate counters
// ============================================================
__global__ void zero_counts_kernel() {
    int t = blockIdx.x * 256 + threadIdx.x;
    if (t < B_ * HWREF) ((unsigned*)g_ccount)[t] = 0;
}

// ============================================================
// Kernel 1b: single coalesced pass over qk in ORIGINAL layout,
// 8 independent float4 loads per thread (MLP=8). Compacts all
// elements >= QTHRESH (~2.3% of N(0,1)) into per-column buffers.
// ============================================================
__global__ void __launch_bounds__(256) qk_scatter_kernel(const float* __restrict__ qk) {
    const float4* __restrict__ src = (const float4*)qk;
    int base = blockIdx.x * (256 * 8) + threadIdx.x;
    float4 v[8];
    #pragma unroll
    for (int k = 0; k < 8; k++) v[k] = src[base + k * 256];
    #pragma unroll
    for (int k = 0; k < 8; k++) {
        if (v[k].x < QTHRESH && v[k].y < QTHRESH &&
            v[k].z < QTHRESH && v[k].w < QTHRESH) continue;
        int f   = base + k * 256;
        int lin = f * 4;
        int j0  = lin & 1023;
        unsigned bn = ((unsigned)lin) >> 10;
        int b = bn >> 14;
        int n = bn & 16383;
        #pragma unroll
        for (int e = 0; e < 4; e++) {
            float val = (e == 0) ? v[k].x : (e == 1) ? v[k].y : (e == 2) ? v[k].z : v[k].w;
            if (val >= QTHRESH) {
                int j = j0 + e;
                unsigned p = atomicAdd(&g_ccount[b][j], 1u);
                if (p < CANDCAP) g_cand[b][j][p] = make_uint2(f2ord(val), (unsigned)n);
            }
        }
    }
}

// ============================================================
// Kernel 2: per-column exact top-32 refine. One CTA per (b,j).
// Main path: candidates from g_cand; nibble-radix narrow to <=128;
// exact pairwise rank (desc value, ties -> lower index ==
// jax.lax.top_k order). Fallback: exact radix over strided column.
// ============================================================
__global__ void __launch_bounds__(256) topk_refine_kernel(const float* __restrict__ qk,
                                                          float* __restrict__ aux_out,
                                                          int write_aux) {
    __shared__ unsigned s_key[RCAP];
    __shared__ int      s_idx[RCAP];
    __shared__ unsigned s_k2[RCAP];
    __shared__ int      s_i2[RCAP];
    __shared__ int      s_c;
    __shared__ unsigned s_hist[16];

    int col = blockIdx.x;
    int b = col >> 10, j = col & 1023;
    int tid = threadIdx.x;

    unsigned maskhi = 0, prefix = 0;
    int krem = K_;
    int shift = 28;
    int cnt, total;

    int C = (int)g_ccount[b][j];
    if (C >= K_ && C <= CANDCAP) {
        for (int i = tid; i < C; i += 256) {
            uint2 c = g_cand[b][j][i];
            s_key[i] = c.x;
            s_idx[i] = (int)c.y;
        }
        cnt = C;
        total = C;
        __syncthreads();
    } else {
        const float* colp = qk + (size_t)b * NBLK * HWREF + j;
        total = NBLK;
        for (; shift >= 0 && total > CANDCAP; shift -= 4) {
            if (tid < 16) s_hist[tid] = 0;
            __syncthreads();
            for (int i = tid; i < NBLK; i += 256) {
                unsigned key = f2ord(colp[(size_t)i * HWREF]);
                if ((key & maskhi) == prefix)
                    atomicAdd(&s_hist[(key >> shift) & 15], 1u);
            }
            __syncthreads();
            int cum = 0, nib = 0;
            for (int n2 = 15; n2 >= 0; n2--) {
                int c = (int)s_hist[n2];
                if (cum + c >= krem) { nib = n2; break; }
                cum += c;
            }
            krem -= cum;
            prefix |= (unsigned)nib << shift;
            maskhi |= 0xFu << shift;
            total = (K_ - krem) + (int)s_hist[nib];
            __syncthreads();
        }
        if (tid == 0) s_c = 0;
        __syncthreads();
        for (int i = tid; i < NBLK; i += 256) {
            unsigned key = f2ord(colp[(size_t)i * HWREF]);
            if (key >= prefix) {
                int p = atomicAdd(&s_c, 1);
                if (p < RCAP) { s_key[p] = key; s_idx[p] = i; }
            }
        }
        __syncthreads();
        cnt = s_c < RCAP ? s_c : RCAP;
        total = cnt;
        __syncthreads();
    }

    for (; shift >= 0 && total > 128; shift -= 4) {
        if (tid < 16) s_hist[tid] = 0;
        __syncthreads();
        for (int i = tid; i < cnt; i += 256) {
            unsigned key = s_key[i];
            if ((key & maskhi) == prefix)
                atomicAdd(&s_hist[(key >> shift) & 15], 1u);
        }
        __syncthreads();
        int cum = 0, nib = 0;
        for (int n2 = 15; n2 >= 0; n2--) {
            int c = (int)s_hist[n2];
            if (cum + c >= krem) { nib = n2; break; }
            cum += c;
        }
        krem -= cum;
        prefix |= (unsigned)nib << shift;
        maskhi |= 0xFu << shift;
        total = (K_ - krem) + (int)s_hist[nib];
        __syncthreads();
    }

    if (tid == 0) s_c = 0;
    __syncthreads();
    for (int i = tid; i < cnt; i += 256) {
        unsigned key = s_key[i];
        if (key >= prefix) {
            int p = atomicAdd(&s_c, 1);
            if (p < RCAP) { s_k2[p] = key; s_i2[p] = s_idx[i]; }
        }
    }
    __syncthreads();
    int C2 = s_c < RCAP ? s_c : RCAP;

    for (int i = tid; i < C2; i += 256) {
        unsigned ki = s_k2[i];
        int      ii = s_i2[i];
        int rank = 0;
        for (int jc = 0; jc < C2; jc++) {
            unsigned kj = s_k2[jc];
            rank += (kj > ki) || (kj == ki && s_i2[jc] < ii);
        }
        if (rank < K_) {
            g_sel[b][j][rank] = ii;
            if (write_aux && rank < KK) {
                int o = (b * HWREF + j) * KK + rank;
                aux_out[MEMOUT_ELEMS + o]                   = (float)ii;
                aux_out[MEMOUT_ELEMS + B_ * HWREF * KK + o] = ord2f(ki);
            }
        }
    }
}

// ============================================================
// Kernel 3: sparse block attention, fp16 K/V (fp32 q, p, accum)
// ============================================================
__global__ void attn_kernel(const float* __restrict__ q_in, float* __restrict__ out) {
    __shared__ float4 q_s4[4][32];
    __shared__ float4 p_s[128];
    __shared__ int    sel[K_];

    int blk = blockIdx.x;
    int b  = blk >> 10, jq = blk & 1023;
    int hr = jq >> 5,   wr = jq & 31;
    int tid = threadIdx.x;

    if (tid < K_) sel[tid] = g_sel[b][jq][tid];
    if (tid < DE) {
        int c = tid;
        const float* qp = q_in + ((b * DE + c) * H_ + hr * 2) * W_ + wr * 2;
        float2 r0 = *(const float2*)qp;
        float2 r1 = *(const float2*)(qp + W_);
        ((float*)q_s4)[0 * DE + c] = r0.x;
        ((float*)q_s4)[1 * DE + c] = r0.y;
        ((float*)q_s4)[2 * DE + c] = r1.x;
        ((float*)q_s4)[3 * DE + c] = r1.y;
    }
    __syncthreads();

    int wid = tid >> 5, lane = tid & 31;
    float4 q0 = q_s4[0][lane];
    float4 q1 = q_s4[1][lane];
    float4 q2 = q_s4[2][lane];
    float4 q3 = q_s4[3][lane];
    const float scale = 0.08838834764831845f;  // 1/sqrt(128)

    // ---- QK: warp-per-key, lane covers 4 channels (uint2 = 4 halves) ----
    #pragma unroll 4
    for (int mm = 0; mm < 16; mm++) {
        int m  = wid * 16 + mm;
        int ks = m >> 2, pm = m & 3;
        int n  = sel[ks];
        const uint2* kp = (const uint2*)(&g_mb_in[b][n][pm][0]);
        uint2 raw = kp[lane];
        float2 f01 = __half22float2(*reinterpret_cast<__half2*>(&raw.x));
        float2 f23 = __half22float2(*reinterpret_cast<__half2*>(&raw.y));
        float a0 = f01.x*q0.x + f01.y*q0.y + f23.x*q0.z + f23.y*q0.w;
        float a1 = f01.x*q1.x + f01.y*q1.y + f23.x*q1.z + f23.y*q1.w;
        float a2 = f01.x*q2.x + f01.y*q2.y + f23.x*q2.z + f23.y*q2.w;
        float a3 = f01.x*q3.x + f01.y*q3.y + f23.x*q3.z + f23.y*q3.w;
        #pragma unroll
        for (int o = 16; o; o >>= 1) {
            a0 += __shfl_xor_sync(0xffffffffu, a0, o);
            a1 += __shfl_xor_sync(0xffffffffu, a1, o);
            a2 += __shfl_xor_sync(0xffffffffu, a2, o);
            a3 += __shfl_xor_sync(0xffffffffu, a3, o);
        }
        if (lane == 0)
            p_s[m] = make_float4(a0 * scale, a1 * scale, a2 * scale, a3 * scale);
    }
    __syncthreads();

    if (wid < 4) {
        int p = wid;
        float* ps = (float*)p_s;
        float x0 = ps[(lane      ) * 4 + p];
        float x1 = ps[(lane + 32 ) * 4 + p];
        float x2 = ps[(lane + 64 ) * 4 + p];
        float x3 = ps[(lane + 96 ) * 4 + p];
        float mx = fmaxf(fmaxf(x0, x1), fmaxf(x2, x3));
        #pragma unroll
        for (int o = 16; o; o >>= 1) mx = fmaxf(mx, __shfl_xor_sync(0xffffffffu, mx, o));
        float e0 = __expf(x0 - mx), e1 = __expf(x1 - mx);
        float e2 = __expf(x2 - mx), e3 = __expf(x3 - mx);
        float sm = e0 + e1 + e2 + e3;
        #pragma unroll
        for (int o = 16; o; o >>= 1) sm += __shfl_xor_sync(0xffffffffu, sm, o);
        float inv = 1.0f / sm;
        ps[(lane      ) * 4 + p] = e0 * inv;
        ps[(lane + 32 ) * 4 + p] = e1 * inv;
        ps[(lane + 64 ) * 4 + p] = e2 * inv;
        ps[(lane + 96 ) * 4 + p] = e3 * inv;
    }
    __syncthreads();

    // ---- PV: thread-per-out-channel, fp16 V, fp32 accum ----
    int c = tid;
    float a0 = 0.f, a1 = 0.f, a2 = 0.f, a3 = 0.f;
    #pragma unroll 4
    for (int ks = 0; ks < K_; ks++) {
        int n = sel[ks];
        const __half* vbase = &g_mb_out[b][n][0][0];
        #pragma unroll
        for (int pm = 0; pm < 4; pm++) {
            float  v  = __half2float(vbase[pm * DOo + c]);
            float4 pw = p_s[ks * 4 + pm];
            a0 += v * pw.x; a1 += v * pw.y; a2 += v * pw.z; a3 += v * pw.w;
        }
    }
    float* ob = out + ((b * DOo + c) * H_ + hr * 2) * W_ + wr * 2;
    *(float2*)ob        = make_float2(a0, a1);
    *(float2*)(ob + W_) = make_float2(a2, a3);
}

// ============================================================
extern "C" void kernel_launch(void* const* d_in, const int* in_sizes, int n_in,
                              void* d_out, int out_size) {
    const float* m_in  = (const float*)d_in[0];
    const float* m_out = (const float*)d_in[1];
    const float* q_in  = (const float*)d_in[2];
    const float* qk    = (const float*)d_in[3];
    float* out = (float*)d_out;

    int write_aux = (out_size >= MEMOUT_ELEMS + 2 * B_ * HWREF * KK) ? 1 : 0;

    // Fork a side stream for the topk chain (reads qk only) so it
    // overlaps with the blockify chain (reads m_in/m_out).
    cudaStream_t s2;
    cudaEvent_t eFork, eJoin;
    cudaStreamCreateWithFlags(&s2, cudaStreamNonBlocking);
    cudaEventCreateWithFlags(&eFork, cudaEventDisableTiming);
    cudaEventCreateWithFlags(&eJoin, cudaEventDisableTiming);

    cudaEventRecord(eFork, 0);
    cudaStreamWaitEvent(s2, eFork, 0);

    // side branch: topk chain
    zero_counts_kernel<<<(B_ * HWREF + 255) / 256, 256, 0, s2>>>();
    qk_scatter_kernel<<<(B_ * NBLK * HWREF) / (1024 * 8), 256, 0, s2>>>(qk);
    topk_refine_kernel<<<B_ * HWREF, 256, 0, s2>>>(qk, out, write_aux);
    cudaEventRecord(eJoin, s2);

    // main branch: blockify chain
    dim3 tb(32, 8);
    blockify_kernel<<<16384, tb>>>(m_in, DE, 0);
    blockify_kernel<<<32768, tb>>>(m_out, DOo, 1);

    // join + attention
    cudaStreamWaitEvent(0, eJoin, 0);
    attn_kernel<<<B_ * HWREF, 256>>>(q_in, out);
}

// round 15
// speedup vs baseline: 1.9645x; 1.0409x over previous
#include <cuda_runtime.h>
#include <cuda_fp16.h>

#define B_ 2
#define DE 128
#define DOo 256
#define T_ 16
#define H_ 64
#define W_ 64
#define NBLK 16384   // T * 32 * 32
#define HWREF 1024   // 32 * 32
#define K_ 32
#define KK 8
#define RCAP 1536
#define CANDCAP 1024
#define QTHRESH 2.0f
#define MEMOUT_ELEMS (B_*DOo*H_*W_)   // 2097152

// ---- scratch (static device globals; no runtime allocation) ----
// fp16 blockified K/V: total 100 MB -> fits L2 (126 MB) during attn.
__device__ __half   g_mb_in[B_][NBLK][4][DE];    // 33.5 MB [b][block][px][c]
__device__ __half   g_mb_out[B_][NBLK][4][DOo];  // 67 MB
__device__ unsigned g_ccount[B_][HWREF];
__device__ uint2    g_cand[B_][HWREF][CANDCAP];  // (ordered key, block idx)
__device__ int      g_sel[B_][HWREF][K_];        // selected blocks (desc-value order)

__device__ __forceinline__ unsigned f2ord(float f) {
    unsigned u = __float_as_uint(f);
    return (u & 0x80000000u) ? ~u : (u | 0x80000000u);
}
__device__ __forceinline__ float ord2f(unsigned k) {
    unsigned u = (k & 0x80000000u) ? (k & 0x7fffffffu) : ~k;
    return __uint_as_float(u);
}

// ============================================================
// Kernel 0: blockify  m[b][c][t][h][w] -> mb[b][n][pm][c] (fp16)
// ============================================================
__global__ void blockify_kernel(const float* __restrict__ in, int D, int is_out) {
    __shared__ float tile[32][33];
    __half* out = is_out ? &g_mb_out[0][0][0][0] : &g_mb_in[0][0][0][0];
    int bx = blockIdx.x;
    int wt = bx & 1;  bx >>= 1;
    int h  = bx & 63; bx >>= 6;
    int t  = bx & 15; bx >>= 4;
    int nct = D >> 5;
    int ct = bx % nct;
    int b  = bx / nct;
    int tx = threadIdx.x, ty = threadIdx.y;
    #pragma unroll
    for (int r = 0; r < 4; r++) {
        int c = (ct << 5) + ty + (r << 3);
        tile[ty + (r << 3)][tx] =
            in[(((b * D + c) * T_ + t) * H_ + h) * W_ + (wt << 5) + tx];
    }
    __syncthreads();
    int hr = h >> 1, im = h & 1;
    int a = tx & 15;
    #pragma unroll
    for (int r = 0; r < 2; r++) {
        int wi = (tx >> 4) | (ty << 1) | (r << 4);   // 0..31, bijective
        int w  = (wt << 5) + wi;
        int wr = w >> 1, jm = w & 1;
        int n  = t * 1024 + hr * 32 + wr;
        int pm = im * 2 + jm;
        __half2 hv = __floats2half2_rn(tile[2 * a][wi], tile[2 * a + 1][wi]);
        *(__half2*)(out + (size_t)((b * NBLK + n) * 4 + pm) * D + (ct << 5) + 2 * a) = hv;
    }
}

// ============================================================
// Kernel 1a: zero the per-column candidate counters
// ============================================================
__global__ void zero_counts_kernel() {
    int t = blockIdx.x * 256 + threadIdx.x;
    if (t < B_ * HWREF) ((unsigned*)g_ccount)[t] = 0;
}

// ============================================================
// Kernel 1b: single coalesced pass over qk (MLP=8), compacting
// elements >= QTHRESH into per-column candidate buffers.
// ============================================================
__global__ void __launch_bounds__(256) qk_scatter_kernel(const float* __restrict__ qk) {
    const float4* __restrict__ src = (const float4*)qk;
    int base = blockIdx.x * (256 * 8) + threadIdx.x;
    float4 v[8];
    #pragma unroll
    for (int k = 0; k < 8; k++) v[k] = src[base + k * 256];
    #pragma unroll
    for (int k = 0; k < 8; k++) {
        if (v[k].x < QTHRESH && v[k].y < QTHRESH &&
            v[k].z < QTHRESH && v[k].w < QTHRESH) continue;
        int f   = base + k * 256;
        int lin = f * 4;
        int j0  = lin & 1023;
        unsigned bn = ((unsigned)lin) >> 10;
        int b = bn >> 14;
        int n = bn & 16383;
        #pragma unroll
        for (int e = 0; e < 4; e++) {
            float val = (e == 0) ? v[k].x : (e == 1) ? v[k].y : (e == 2) ? v[k].z : v[k].w;
            if (val >= QTHRESH) {
                int j = j0 + e;
                unsigned p = atomicAdd(&g_ccount[b][j], 1u);
                if (p < CANDCAP) g_cand[b][j][p] = make_uint2(f2ord(val), (unsigned)n);
            }
        }
    }
}

// ============================================================
// Kernel 2: per-column exact top-32 refine (jax.lax.top_k order)
// ============================================================
__global__ void __launch_bounds__(256) topk_refine_kernel(const float* __restrict__ qk,
                                                          float* __restrict__ aux_out,
                                                          int write_aux) {
    __shared__ unsigned s_key[RCAP];
    __shared__ int      s_idx[RCAP];
    __shared__ unsigned s_k2[RCAP];
    __shared__ int      s_i2[RCAP];
    __shared__ int      s_c;
    __shared__ unsigned s_hist[16];

    int col = blockIdx.x;
    int b = col >> 10, j = col & 1023;
    int tid = threadIdx.x;

    unsigned maskhi = 0, prefix = 0;
    int krem = K_;
    int shift = 28;
    int cnt, total;

    int C = (int)g_ccount[b][j];
    if (C >= K_ && C <= CANDCAP) {
        for (int i = tid; i < C; i += 256) {
            uint2 c = g_cand[b][j][i];
            s_key[i] = c.x;
            s_idx[i] = (int)c.y;
        }
        cnt = C;
        total = C;
        __syncthreads();
    } else {
        const float* colp = qk + (size_t)b * NBLK * HWREF + j;
        total = NBLK;
        for (; shift >= 0 && total > CANDCAP; shift -= 4) {
            if (tid < 16) s_hist[tid] = 0;
            __syncthreads();
            for (int i = tid; i < NBLK; i += 256) {
                unsigned key = f2ord(colp[(size_t)i * HWREF]);
                if ((key & maskhi) == prefix)
                    atomicAdd(&s_hist[(key >> shift) & 15], 1u);
            }
            __syncthreads();
            int cum = 0, nib = 0;
            for (int n2 = 15; n2 >= 0; n2--) {
                int c = (int)s_hist[n2];
                if (cum + c >= krem) { nib = n2; break; }
                cum += c;
            }
            krem -= cum;
            prefix |= (unsigned)nib << shift;
            maskhi |= 0xFu << shift;
            total = (K_ - krem) + (int)s_hist[nib];
            __syncthreads();
        }
        if (tid == 0) s_c = 0;
        __syncthreads();
        for (int i = tid; i < NBLK; i += 256) {
            unsigned key = f2ord(colp[(size_t)i * HWREF]);
            if (key >= prefix) {
                int p = atomicAdd(&s_c, 1);
                if (p < RCAP) { s_key[p] = key; s_idx[p] = i; }
            }
        }
        __syncthreads();
        cnt = s_c < RCAP ? s_c : RCAP;
        total = cnt;
        __syncthreads();
    }

    for (; shift >= 0 && total > 128; shift -= 4) {
        if (tid < 16) s_hist[tid] = 0;
        __syncthreads();
        for (int i = tid; i < cnt; i += 256) {
            unsigned key = s_key[i];
            if ((key & maskhi) == prefix)
                atomicAdd(&s_hist[(key >> shift) & 15], 1u);
        }
        __syncthreads();
        int cum = 0, nib = 0;
        for (int n2 = 15; n2 >= 0; n2--) {
            int c = (int)s_hist[n2];
            if (cum + c >= krem) { nib = n2; break; }
            cum += c;
        }
        krem -= cum;
        prefix |= (unsigned)nib << shift;
        maskhi |= 0xFu << shift;
        total = (K_ - krem) + (int)s_hist[nib];
        __syncthreads();
    }

    if (tid == 0) s_c = 0;
    __syncthreads();
    for (int i = tid; i < cnt; i += 256) {
        unsigned key = s_key[i];
        if (key >= prefix) {
            int p = atomicAdd(&s_c, 1);
            if (p < RCAP) { s_k2[p] = key; s_i2[p] = s_idx[i]; }
        }
    }
    __syncthreads();
    int C2 = s_c < RCAP ? s_c : RCAP;

    for (int i = tid; i < C2; i += 256) {
        unsigned ki = s_k2[i];
        int      ii = s_i2[i];
        int rank = 0;
        for (int jc = 0; jc < C2; jc++) {
            unsigned kj = s_k2[jc];
            rank += (kj > ki) || (kj == ki && s_i2[jc] < ii);
        }
        if (rank < K_) {
            g_sel[b][j][rank] = ii;
            if (write_aux && rank < KK) {
                int o = (b * HWREF + j) * KK + rank;
                aux_out[MEMOUT_ELEMS + o]                   = (float)ii;
                aux_out[MEMOUT_ELEMS + B_ * HWREF * KK + o] = ord2f(ki);
            }
        }
    }
}

// ============================================================
// Kernel 3: sparse block attention, fp16 K/V.
// PV restructured: split-ks + half2.
//   thread = (half = tid>>7, c2 = tid&127); channels {2c2, 2c2+1}
//   half 0 -> ks 0..15, half 1 -> ks 16..31
//   per iter: one LDG.32 (half2 V) + 8 FFMA  (was: 2x LDG.U16 + 8 FFMA
//   over 2 iters) -> half the loop trips, full 128B/warp loads.
//   Partials combined via padded smem (stride 9 -> conflict-free).
// ============================================================
__global__ void __launch_bounds__(256) attn_kernel(const float* __restrict__ q_in,
                                                   float* __restrict__ out) {
    __shared__ float4 q_s4[4][32];
    __shared__ float4 p_s[128];
    __shared__ int    sel[K_];
    __shared__ float  s_red[128][9];   // [c2][8 partials + pad]

    int blk = blockIdx.x;
    int b  = blk >> 10, jq = blk & 1023;
    int hr = jq >> 5,   wr = jq & 31;
    int tid = threadIdx.x;

    if (tid < K_) sel[tid] = g_sel[b][jq][tid];
    if (tid < DE) {
        int c = tid;
        const float* qp = q_in + ((b * DE + c) * H_ + hr * 2) * W_ + wr * 2;
        float2 r0 = *(const float2*)qp;
        float2 r1 = *(const float2*)(qp + W_);
        ((float*)q_s4)[0 * DE + c] = r0.x;
        ((float*)q_s4)[1 * DE + c] = r0.y;
        ((float*)q_s4)[2 * DE + c] = r1.x;
        ((float*)q_s4)[3 * DE + c] = r1.y;
    }
    __syncthreads();

    int wid = tid >> 5, lane = tid & 31;
    float4 q0 = q_s4[0][lane];
    float4 q1 = q_s4[1][lane];
    float4 q2 = q_s4[2][lane];
    float4 q3 = q_s4[3][lane];
    const float scale = 0.08838834764831845f;  // 1/sqrt(128)

    // ---- QK: warp-per-key, lane covers 4 channels ----
    #pragma unroll 4
    for (int mm = 0; mm < 16; mm++) {
        int m  = wid * 16 + mm;
        int ks = m >> 2, pm = m & 3;
        int n  = sel[ks];
        const uint2* kp = (const uint2*)(&g_mb_in[b][n][pm][0]);
        uint2 raw = kp[lane];
        float2 f01 = __half22float2(*reinterpret_cast<__half2*>(&raw.x));
        float2 f23 = __half22float2(*reinterpret_cast<__half2*>(&raw.y));
        float a0 = f01.x*q0.x + f01.y*q0.y + f23.x*q0.z + f23.y*q0.w;
        float a1 = f01.x*q1.x + f01.y*q1.y + f23.x*q1.z + f23.y*q1.w;
        float a2 = f01.x*q2.x + f01.y*q2.y + f23.x*q2.z + f23.y*q2.w;
        float a3 = f01.x*q3.x + f01.y*q3.y + f23.x*q3.z + f23.y*q3.w;
        #pragma unroll
        for (int o = 16; o; o >>= 1) {
            a0 += __shfl_xor_sync(0xffffffffu, a0, o);
            a1 += __shfl_xor_sync(0xffffffffu, a1, o);
            a2 += __shfl_xor_sync(0xffffffffu, a2, o);
            a3 += __shfl_xor_sync(0xffffffffu, a3, o);
        }
        if (lane == 0)
            p_s[m] = make_float4(a0 * scale, a1 * scale, a2 * scale, a3 * scale);
    }
    __syncthreads();

    // ---- softmax over m (128) per query pixel ----
    if (wid < 4) {
        int p = wid;
        float* ps = (float*)p_s;
        float x0 = ps[(lane      ) * 4 + p];
        float x1 = ps[(lane + 32 ) * 4 + p];
        float x2 = ps[(lane + 64 ) * 4 + p];
        float x3 = ps[(lane + 96 ) * 4 + p];
        float mx = fmaxf(fmaxf(x0, x1), fmaxf(x2, x3));
        #pragma unroll
        for (int o = 16; o; o >>= 1) mx = fmaxf(mx, __shfl_xor_sync(0xffffffffu, mx, o));
        float e0 = __expf(x0 - mx), e1 = __expf(x1 - mx);
        float e2 = __expf(x2 - mx), e3 = __expf(x3 - mx);
        float sm = e0 + e1 + e2 + e3;
        #pragma unroll
        for (int o = 16; o; o >>= 1) sm += __shfl_xor_sync(0xffffffffu, sm, o);
        float inv = 1.0f / sm;
        ps[(lane      ) * 4 + p] = e0 * inv;
        ps[(lane + 32 ) * 4 + p] = e1 * inv;
        ps[(lane + 64 ) * 4 + p] = e2 * inv;
        ps[(lane + 96 ) * 4 + p] = e3 * inv;
    }
    __syncthreads();

    // ---- PV: split-ks + half2 ----
    int half = tid >> 7;       // 0 or 1
    int c2   = tid & 127;      // channel pair: channels 2c2, 2c2+1
    float acc[8] = {0.f, 0.f, 0.f, 0.f, 0.f, 0.f, 0.f, 0.f};  // [ch][px]
    int ks0 = half * 16;
    #pragma unroll 4
    for (int ks = ks0; ks < ks0 + 16; ks++) {
        int n = sel[ks];
        const __half* vbase = &g_mb_out[b][n][0][0];
        #pragma unroll
        for (int pm = 0; pm < 4; pm++) {
            __half2 hv = *(const __half2*)(vbase + pm * DOo + 2 * c2);
            float2 vf = __half22float2(hv);
            float4 pw = p_s[ks * 4 + pm];
            acc[0] += vf.x * pw.x; acc[1] += vf.x * pw.y;
            acc[2] += vf.x * pw.z; acc[3] += vf.x * pw.w;
            acc[4] += vf.y * pw.x; acc[5] += vf.y * pw.y;
            acc[6] += vf.y * pw.z; acc[7] += vf.y * pw.w;
        }
    }
    if (half == 1) {
        #pragma unroll
        for (int i = 0; i < 8; i++) s_red[c2][i] = acc[i];
    }
    __syncthreads();
    if (half == 0) {
        #pragma unroll
        for (int i = 0; i < 8; i++) acc[i] += s_red[c2][i];
        int c0 = 2 * c2;
        float* ob0 = out + ((b * DOo + c0) * H_ + hr * 2) * W_ + wr * 2;
        *(float2*)ob0        = make_float2(acc[0], acc[1]);
        *(float2*)(ob0 + W_) = make_float2(acc[2], acc[3]);
        float* ob1 = ob0 + (size_t)H_ * W_;   // channel c0+1
        *(float2*)ob1        = make_float2(acc[4], acc[5]);
        *(float2*)(ob1 + W_) = make_float2(acc[6], acc[7]);
    }
}

// ============================================================
extern "C" void kernel_launch(void* const* d_in, const int* in_sizes, int n_in,
                              void* d_out, int out_size) {
    const float* m_in  = (const float*)d_in[0];
    const float* m_out = (const float*)d_in[1];
    const float* q_in  = (const float*)d_in[2];
    const float* qk    = (const float*)d_in[3];
    float* out = (float*)d_out;

    int write_aux = (out_size >= MEMOUT_ELEMS + 2 * B_ * HWREF * KK) ? 1 : 0;

    // Fork a side stream for the topk chain (reads qk only) so it
    // overlaps with the blockify chain (reads m_in/m_out).
    cudaStream_t s2;
    cudaEvent_t eFork, eJoin;
    cudaStreamCreateWithFlags(&s2, cudaStreamNonBlocking);
    cudaEventCreateWithFlags(&eFork, cudaEventDisableTiming);
    cudaEventCreateWithFlags(&eJoin, cudaEventDisableTiming);

    cudaEventRecord(eFork, 0);
    cudaStreamWaitEvent(s2, eFork, 0);

    // side branch: topk chain
    zero_counts_kernel<<<(B_ * HWREF + 255) / 256, 256, 0, s2>>>();
    qk_scatter_kernel<<<(B_ * NBLK * HWREF) / (1024 * 8), 256, 0, s2>>>(qk);
    topk_refine_kernel<<<B_ * HWREF, 256, 0, s2>>>(qk, out, write_aux);
    cudaEventRecord(eJoin, s2);

    // main branch: blockify chain
    dim3 tb(32, 8);
    blockify_kernel<<<16384, tb>>>(m_in, DE, 0);
    blockify_kernel<<<32768, tb>>>(m_out, DOo, 1);

    // join + attention
    cudaStreamWaitEvent(0, eJoin, 0);
    attn_kernel<<<B_ * HWREF, 256>>>(q_in, out);
}